// round 16
// baseline (speedup 1.0000x reference)
#include <cuda_runtime.h>
#include <cstdint>

#define NROWS 16384
#define DDIM  256            // bytes per row in fp8
#define TM 128
#define TN 128
#define TOTAL_TILES ((NROWS / TM) * (NROWS / TN))
#define NCTA 296             // 2 per SM
#define QSCALE 16.0f
#define LN2 0.6931471805599453f

// dynamic smem: A single buffer 32KB, B double buffer 2x32KB, reduce pad
#define SM_A  0
#define SM_B0 32768
#define SM_RED 98304
#define SM_TOTAL (98304 + 256)

__device__ uint8_t g_imgQ[NROWS * DDIM];
__device__ uint8_t g_txtQ[NROWS * DDIM];
__device__ double g_partials[NCTA];

// ---------------------------------------------------------------------------
// helpers
// ---------------------------------------------------------------------------
static __device__ __forceinline__ uint32_t smem_u32(const void* p) {
    return (uint32_t)__cvta_generic_to_shared(p);
}
static __device__ __forceinline__ uint32_t swz(uint32_t o) {
    return o ^ ((o >> 3) & 0x70);
}
static __device__ __forceinline__ void cpa16(uint32_t dst, const void* src) {
    asm volatile("cp.async.cg.shared.global [%0], [%1], 16;" :: "r"(dst), "l"(src) : "memory");
}
static __device__ __forceinline__ void cpa_commit() {
    asm volatile("cp.async.commit_group;" ::: "memory");
}
static __device__ __forceinline__ void cpa_wait0() {
    asm volatile("cp.async.wait_group 0;" ::: "memory");
}
// ldmatrix with compile-time immediate offset (keeps address math out of the loop)
template <int IMM>
static __device__ __forceinline__ void ldsm_x4i(uint32_t& r0, uint32_t& r1,
                                                uint32_t& r2, uint32_t& r3,
                                                uint32_t addr) {
    asm volatile("ldmatrix.sync.aligned.m8n8.x4.shared.b16 {%0,%1,%2,%3}, [%4+%5];\n"
                 : "=r"(r0), "=r"(r1), "=r"(r2), "=r"(r3) : "r"(addr), "n"(IMM));
}
static __device__ __forceinline__ void mma_fp8(float& c0, float& c1, float& c2, float& c3,
                                               uint32_t a0, uint32_t a1, uint32_t a2, uint32_t a3,
                                               uint32_t b0, uint32_t b1) {
    asm volatile(
        "mma.sync.aligned.m16n8k32.row.col.f32.e4m3.e4m3.f32 "
        "{%0,%1,%2,%3}, {%4,%5,%6,%7}, {%8,%9}, {%0,%1,%2,%3};\n"
        : "+f"(c0), "+f"(c1), "+f"(c2), "+f"(c3)
        : "r"(a0), "r"(a1), "r"(a2), "r"(a3), "r"(b0), "r"(b1));
}
// D = A*B + 0  (no dependence on prior acc; kills the per-tile acc clear)
static __device__ __forceinline__ void mma_fp8_set(float& d0, float& d1, float& d2, float& d3,
                                                   uint32_t a0, uint32_t a1, uint32_t a2, uint32_t a3,
                                                   uint32_t b0, uint32_t b1) {
    asm volatile(
        "mma.sync.aligned.m16n8k32.row.col.f32.e4m3.e4m3.f32 "
        "{%0,%1,%2,%3}, {%4,%5,%6,%7}, {%8,%9}, {%10,%11,%12,%13};\n"
        : "=f"(d0), "=f"(d1), "=f"(d2), "=f"(d3)
        : "r"(a0), "r"(a1), "r"(a2), "r"(a3), "r"(b0), "r"(b1),
          "f"(0.0f), "f"(0.0f), "f"(0.0f), "f"(0.0f));
}
static __device__ __forceinline__ uint32_t f2e4m3x2(float lo, float hi) {
    uint16_t r;
    asm("cvt.rn.satfinite.e4m3x2.f32 %0, %1, %2;" : "=h"(r) : "f"(hi), "f"(lo));
    return (uint32_t)r;
}
static __device__ __forceinline__ float ex2_approx(float x) {
    float r; asm("ex2.approx.ftz.f32 %0, %1;" : "=f"(r) : "f"(x)); return r;
}
static __device__ __forceinline__ float lg2_approx(float x) {
    float r; asm("lg2.approx.ftz.f32 %0, %1;" : "=f"(r) : "f"(x)); return r;
}

// load one 128x256B tile into swizzled smem (8 x 16B chunks per thread)
static __device__ __forceinline__ void load_tile(uint32_t sdst, const uint8_t* g, int tid) {
#pragma unroll
    for (int c = 0; c < 8; ++c) {
        int idx = c * 256 + tid;
        int row = idx >> 4;
        int kc  = idx & 15;
        uint32_t soff = ((uint32_t)(kc >> 3) << 14) + swz((uint32_t)(row * 128 + (kc & 7) * 16));
        cpa16(sdst + soff, g + row * 256 + kc * 16);
    }
}

// ---------------------------------------------------------------------------
// Kernel 1: L2-normalize rows, quantize to e4m3. 1 warp/row.
// ---------------------------------------------------------------------------
__global__ void normq_kernel(const float* __restrict__ img,
                             const float* __restrict__ txt) {
    int warp = threadIdx.x >> 5;
    int lane = threadIdx.x & 31;
    int row  = blockIdx.x * 8 + warp;
    const float* src = (blockIdx.y == 0) ? img : txt;
    uint8_t* dst     = (blockIdx.y == 0) ? g_imgQ : g_txtQ;

    const float4* p = reinterpret_cast<const float4*>(src + (size_t)row * DDIM + lane * 8);
    float4 v0 = p[0];
    float4 v1 = p[1];
    float ss = v0.x * v0.x + v0.y * v0.y + v0.z * v0.z + v0.w * v0.w
             + v1.x * v1.x + v1.y * v1.y + v1.z * v1.z + v1.w * v1.w;
#pragma unroll
    for (int o = 16; o > 0; o >>= 1) ss += __shfl_xor_sync(0xffffffffu, ss, o);
    float s = QSCALE / fmaxf(sqrtf(ss), 1e-12f);

    uint32_t q01 = f2e4m3x2(v0.x * s, v0.y * s);
    uint32_t q23 = f2e4m3x2(v0.z * s, v0.w * s);
    uint32_t q45 = f2e4m3x2(v1.x * s, v1.y * s);
    uint32_t q67 = f2e4m3x2(v1.z * s, v1.w * s);
    uint2 w;
    w.x = q01 | (q23 << 16);
    w.y = q45 | (q67 << 16);
    *reinterpret_cast<uint2*>(dst + (size_t)row * DDIM + lane * 8) = w;
}

// ---------------------------------------------------------------------------
// Kernel 2: persistent fp8 GEMM, 2 CTAs/SM, A resident, B double-buffered.
// All 24 LDSM base addresses precomputed in registers; stage offset is a
// compile-time immediate. Epilogue: direct log2 softplus, 1 lg2 / 16 logits,
// two independent accumulation chains. D=A*B+0 on first k-step.
// ---------------------------------------------------------------------------
__global__ __launch_bounds__(256, 2) void siglip_fp8v10(const float* __restrict__ tprime,
                                                        const float* __restrict__ biasp) {
    extern __shared__ char smem[];
    const uint32_t sb = smem_u32(smem);
    const int tid  = threadIdx.x;
    const int lane = tid & 31;
    const int wid  = tid >> 5;
    const int wr   = wid >> 1;   // 0..3: 32-row slab
    const int wc   = wid & 1;    // 0..1: 64-col slab
    const int cta  = blockIdx.x;

    const int t0 = (int)(((long long)cta * TOTAL_TILES) / NCTA);
    const int t1 = (int)(((long long)(cta + 1) * TOTAL_TILES) / NCTA);

    const float scaleF = __expf(*tprime) * (1.0f / (QSCALE * QSCALE));
    const float bias   = *biasp;
    const float s2 = 1.4426950408889634f * scaleF;   // log2 e * scale
    const float b2 = 1.4426950408889634f * bias;

    // ldmatrix coordinate bases (layout verified R3-R15)
    const int rA0 = wr * 32 + (lane & 7) + (lane & 8);
    const int kAf = (lane & 16);
    const int nB0 = wc * 64 + (lane & 7) + ((lane & 16) >> 1);
    const int kBf = (lane & 8) * 2;

    const uint32_t maskA = (uint32_t)((rA0 & 7) << 4);
    const uint32_t maskB = (uint32_t)((nB0 & 7) << 4);

    // --- A LDSM addresses: 8 regs, tile-invariant (A smem buffer is fixed) ---
    // aAddr[mi][j] : mi = m-tile (0/1), j = ks&3 ; +16KB stage via immediate.
    uint32_t aAddr[2][4];
#pragma unroll
    for (int j = 0; j < 4; ++j) {
        uint32_t kc = ((uint32_t)(j * 32 + kAf)) ^ maskA;
        aAddr[0][j] = sb + SM_A + (uint32_t)(rA0 * 128) + kc;
        aAddr[1][j] = aAddr[0][j] + 16 * 128;
    }
    // --- B LDSM addresses: 16 regs, toggled by ±32KB per tile ---
    // bAddr[np][j] for current B buffer.
    uint32_t bAddr[4][4];
#pragma unroll
    for (int np = 0; np < 4; ++np)
#pragma unroll
        for (int j = 0; j < 4; ++j) {
            uint32_t kc = ((uint32_t)(j * 32 + kBf)) ^ maskB;
            bAddr[np][j] = sb + SM_B0 + (uint32_t)((nB0 + np * 16) * 128) + kc;
        }
    // start in buffer (t0 & 1)
    if (t0 & 1) {
#pragma unroll
        for (int np = 0; np < 4; ++np)
#pragma unroll
            for (int j = 0; j < 4; ++j) bAddr[np][j] += 32768u;
    }

    float acc[64];

    // prologue: A(panel of t0) + B(t0)
    {
        const uint8_t* Ag = g_imgQ + (size_t)(t0 >> 7) * TM * DDIM;
        const uint8_t* Bg = g_txtQ + (size_t)(t0 & 127) * TN * DDIM;
        load_tile(sb + SM_A, Ag, tid);
        load_tile(sb + SM_B0 + (uint32_t)(t0 & 1) * 32768u, Bg, tid);
        cpa_commit();
        cpa_wait0();
        __syncthreads();
    }

    double dsum = 0.0;

    for (int t = t0; t < t1; ++t) {
        const bool pf = (t + 1 < t1);
        const bool pchange = pf && (((t + 1) >> 7) != (t >> 7));

        if (pf) {
            const uint8_t* Bg = g_txtQ + (size_t)((t + 1) & 127) * TN * DDIM;
            load_tile(sb + SM_B0 + (uint32_t)((t + 1) & 1) * 32768u, Bg, tid);
            cpa_commit();
        }

        // k-loop: 8 steps of k=32B; all addresses are reg + compile-time imm.
#pragma unroll
        for (int ks = 0; ks < 8; ++ks) {
            constexpr int STG_TBL[8] = {0, 0, 0, 0, 16384, 16384, 16384, 16384};
            const int j = ks & 3;

            uint32_t a[2][4];
            if (ks < 4) {
                ldsm_x4i<0>(a[0][0], a[0][1], a[0][2], a[0][3], aAddr[0][j]);
                ldsm_x4i<0>(a[1][0], a[1][1], a[1][2], a[1][3], aAddr[1][j]);
            } else {
                ldsm_x4i<16384>(a[0][0], a[0][1], a[0][2], a[0][3], aAddr[0][j]);
                ldsm_x4i<16384>(a[1][0], a[1][1], a[1][2], a[1][3], aAddr[1][j]);
            }
#pragma unroll
            for (int np = 0; np < 4; ++np) {
                uint32_t b0, b1, b2x, b3;
                if (ks < 4) {
                    ldsm_x4i<0>(b0, b1, b2x, b3, bAddr[np][j]);
                } else {
                    ldsm_x4i<16384>(b0, b1, b2x, b3, bAddr[np][j]);
                }
#pragma unroll
                for (int mi = 0; mi < 2; ++mi) {
                    float* c0 = &acc[mi * 32 + (2 * np) * 4];
                    float* c1 = &acc[mi * 32 + (2 * np + 1) * 4];
                    if (ks == 0) {
                        mma_fp8_set(c0[0], c0[1], c0[2], c0[3],
                                    a[mi][0], a[mi][1], a[mi][2], a[mi][3], b0, b1);
                        mma_fp8_set(c1[0], c1[1], c1[2], c1[3],
                                    a[mi][0], a[mi][1], a[mi][2], a[mi][3], b2x, b3);
                    } else {
                        mma_fp8(c0[0], c0[1], c0[2], c0[3],
                                a[mi][0], a[mi][1], a[mi][2], a[mi][3], b0, b1);
                        mma_fp8(c1[0], c1[1], c1[2], c1[3],
                                a[mi][0], a[mi][1], a[mi][2], a[mi][3], b2x, b3);
                    }
                }
            }
        }

        // epilogue: softplus(z) = ln2 * log2(1 + 2^zt); product over 16
        // (bounded ~2^126) -> one lg2 per 16 logits; two independent chains.
        {
            float fsumA = 0.0f, fsumB = 0.0f;   // log2 units
#pragma unroll
            for (int e = 0; e < 64; e += 32) {
#pragma unroll
                for (int h = 0; h < 2; ++h) {
                    const int b = e + h * 16;
                    float p = 1.0f + ex2_approx(fmaf(s2, acc[b + 0], b2));
#pragma unroll
                    for (int q = 1; q < 16; ++q) {
                        float u = ex2_approx(fmaf(s2, acc[b + q], b2));
                        p = fmaf(p, u, p);
                    }
                    if (h == 0) fsumA += lg2_approx(p);
                    else        fsumB += lg2_approx(p);
                }
            }
            dsum += (double)(LN2 * (fsumA + fsumB));
        }

        // exact diagonal correction: softplus(-z) - softplus(z) = -z
        if ((t >> 7) == (t & 127)) {
#pragma unroll
            for (int e = 0; e < 64; ++e) {
                const int mi = e >> 5, ng = (e >> 2) & 7, q = e & 3;
                const int r = wr * 32 + mi * 16 + (lane >> 2) + 8 * (q >> 1);
                const int cI = wc * 64 + ng * 8 + 2 * (lane & 3) + (q & 1);
                if (r == cI) {
                    float z = fmaf(scaleF, acc[e], bias);
                    dsum -= (double)z;
                }
            }
        }

        // toggle B buffer addresses for next tile (16 IADD, replaces per-LDSM math)
        if (pf) {
            const uint32_t delta = ((t & 1) ? (uint32_t)-32768 : 32768u);
#pragma unroll
            for (int np = 0; np < 4; ++np)
#pragma unroll
                for (int j = 0; j < 4; ++j) bAddr[np][j] += delta;
            cpa_wait0();
        }
        __syncthreads();

        if (pchange) {   // rare: reload A panel (at most once per CTA)
            const uint8_t* Ag = g_imgQ + (size_t)((t + 1) >> 7) * TM * DDIM;
            load_tile(sb + SM_A, Ag, tid);
            cpa_commit();
            cpa_wait0();
            __syncthreads();
        }
    }

    // deterministic block reduction
#pragma unroll
    for (int o = 16; o > 0; o >>= 1) dsum += __shfl_xor_sync(0xffffffffu, dsum, o);
    double* red = reinterpret_cast<double*>(smem + SM_RED);
    if (lane == 0) red[wid] = dsum;
    __syncthreads();
    if (tid == 0) {
        double s = 0.0;
#pragma unroll
        for (int k = 0; k < 8; ++k) s += red[k];
        g_partials[cta] = s;
    }
}

// ---------------------------------------------------------------------------
// Kernel 3: deterministic final reduction.
// ---------------------------------------------------------------------------
__global__ void reduce_kernel(float* __restrict__ out) {
    __shared__ double sh[512];
    int t = threadIdx.x;
    sh[t]       = (t < NCTA) ? g_partials[t] : 0.0;
    sh[t + 256] = (t + 256 < NCTA) ? g_partials[t + 256] : 0.0;
    __syncthreads();
    if (t < 256) sh[t] += sh[t + 256];
    __syncthreads();
    for (int o = 128; o > 0; o >>= 1) {
        if (t < o) sh[t] += sh[t + o];
        __syncthreads();
    }
    if (t == 0) out[0] = (float)(sh[0] / (double)NROWS);
}

extern "C" void kernel_launch(void* const* d_in, const int* in_sizes, int n_in,
                              void* d_out, int out_size) {
    const float* img    = (const float*)d_in[0];
    const float* txt    = (const float*)d_in[1];
    const float* tprime = (const float*)d_in[2];
    const float* bias   = (const float*)d_in[3];
    float* out = (float*)d_out;

    cudaFuncSetAttribute((const void*)siglip_fp8v10,
                         cudaFuncAttributeMaxDynamicSharedMemorySize, SM_TOTAL);

    normq_kernel<<<dim3(NROWS / 8, 2), 256>>>(img, txt);
    siglip_fp8v10<<<NCTA, 256, SM_TOTAL>>>(tprime, bias);
    reduce_kernel<<<1, 256>>>(out);
}

// round 17
// speedup vs baseline: 1.1015x; 1.1015x over previous
#include <cuda_runtime.h>
#include <cstdint>

#define NROWS 16384
#define DDIM  256            // bytes per row in fp8
#define TM 128
#define TN 128
#define TOTAL_TILES ((NROWS / TM) * (NROWS / TN))
#define NCTA 296             // 2 per SM
#define QSCALE 16.0f
#define LN2 0.6931471805599453f

// dynamic smem: A single buffer 32KB, B double buffer 2x32KB, reduce pad
#define SM_A  0
#define SM_B0 32768
#define SM_RED 98304
#define SM_TOTAL (98304 + 256)

__device__ uint8_t g_imgQ[NROWS * DDIM];
__device__ uint8_t g_txtQ[NROWS * DDIM];
__device__ double g_partials[NCTA];

// ---------------------------------------------------------------------------
// helpers
// ---------------------------------------------------------------------------
static __device__ __forceinline__ uint32_t smem_u32(const void* p) {
    return (uint32_t)__cvta_generic_to_shared(p);
}
static __device__ __forceinline__ uint32_t swz(uint32_t o) {
    return o ^ ((o >> 3) & 0x70);
}
static __device__ __forceinline__ void cpa16(uint32_t dst, const void* src) {
    asm volatile("cp.async.cg.shared.global [%0], [%1], 16;" :: "r"(dst), "l"(src) : "memory");
}
static __device__ __forceinline__ void cpa_commit() {
    asm volatile("cp.async.commit_group;" ::: "memory");
}
static __device__ __forceinline__ void cpa_wait0() {
    asm volatile("cp.async.wait_group 0;" ::: "memory");
}
static __device__ __forceinline__ void ldsm_x4(uint32_t& r0, uint32_t& r1,
                                               uint32_t& r2, uint32_t& r3,
                                               uint32_t addr) {
    asm volatile("ldmatrix.sync.aligned.m8n8.x4.shared.b16 {%0,%1,%2,%3}, [%4];\n"
                 : "=r"(r0), "=r"(r1), "=r"(r2), "=r"(r3) : "r"(addr));
}
static __device__ __forceinline__ void mma_fp8(float& c0, float& c1, float& c2, float& c3,
                                               uint32_t a0, uint32_t a1, uint32_t a2, uint32_t a3,
                                               uint32_t b0, uint32_t b1) {
    asm volatile(
        "mma.sync.aligned.m16n8k32.row.col.f32.e4m3.e4m3.f32 "
        "{%0,%1,%2,%3}, {%4,%5,%6,%7}, {%8,%9}, {%0,%1,%2,%3};\n"
        : "+f"(c0), "+f"(c1), "+f"(c2), "+f"(c3)
        : "r"(a0), "r"(a1), "r"(a2), "r"(a3), "r"(b0), "r"(b1));
}
// D = A*B + 0  (no dependence on prior acc; kills the per-tile acc clear)
static __device__ __forceinline__ void mma_fp8_set(float& d0, float& d1, float& d2, float& d3,
                                                   uint32_t a0, uint32_t a1, uint32_t a2, uint32_t a3,
                                                   uint32_t b0, uint32_t b1) {
    asm volatile(
        "mma.sync.aligned.m16n8k32.row.col.f32.e4m3.e4m3.f32 "
        "{%0,%1,%2,%3}, {%4,%5,%6,%7}, {%8,%9}, {%10,%11,%12,%13};\n"
        : "=f"(d0), "=f"(d1), "=f"(d2), "=f"(d3)
        : "r"(a0), "r"(a1), "r"(a2), "r"(a3), "r"(b0), "r"(b1),
          "f"(0.0f), "f"(0.0f), "f"(0.0f), "f"(0.0f));
}
static __device__ __forceinline__ uint32_t f2e4m3x2(float lo, float hi) {
    uint16_t r;
    asm("cvt.rn.satfinite.e4m3x2.f32 %0, %1, %2;" : "=h"(r) : "f"(hi), "f"(lo));
    return (uint32_t)r;
}
static __device__ __forceinline__ float ex2_approx(float x) {
    float r; asm("ex2.approx.ftz.f32 %0, %1;" : "=f"(r) : "f"(x)); return r;
}
static __device__ __forceinline__ float lg2_approx(float x) {
    float r; asm("lg2.approx.ftz.f32 %0, %1;" : "=f"(r) : "f"(x)); return r;
}

// load one 128x256B tile into swizzled smem (8 x 16B chunks per thread)
static __device__ __forceinline__ void load_tile(uint32_t sdst, const uint8_t* g, int tid) {
#pragma unroll
    for (int c = 0; c < 8; ++c) {
        int idx = c * 256 + tid;
        int row = idx >> 4;
        int kc  = idx & 15;
        uint32_t soff = ((uint32_t)(kc >> 3) << 14) + swz((uint32_t)(row * 128 + (kc & 7) * 16));
        cpa16(sdst + soff, g + row * 256 + kc * 16);
    }
}

// ---------------------------------------------------------------------------
// Kernel 1: L2-normalize rows, quantize to e4m3. 1 warp/row.
// ---------------------------------------------------------------------------
__global__ void normq_kernel(const float* __restrict__ img,
                             const float* __restrict__ txt) {
    int warp = threadIdx.x >> 5;
    int lane = threadIdx.x & 31;
    int row  = blockIdx.x * 8 + warp;
    const float* src = (blockIdx.y == 0) ? img : txt;
    uint8_t* dst     = (blockIdx.y == 0) ? g_imgQ : g_txtQ;

    const float4* p = reinterpret_cast<const float4*>(src + (size_t)row * DDIM + lane * 8);
    float4 v0 = p[0];
    float4 v1 = p[1];
    float ss = v0.x * v0.x + v0.y * v0.y + v0.z * v0.z + v0.w * v0.w
             + v1.x * v1.x + v1.y * v1.y + v1.z * v1.z + v1.w * v1.w;
#pragma unroll
    for (int o = 16; o > 0; o >>= 1) ss += __shfl_xor_sync(0xffffffffu, ss, o);
    float s = QSCALE / fmaxf(sqrtf(ss), 1e-12f);

    uint32_t q01 = f2e4m3x2(v0.x * s, v0.y * s);
    uint32_t q23 = f2e4m3x2(v0.z * s, v0.w * s);
    uint32_t q45 = f2e4m3x2(v1.x * s, v1.y * s);
    uint32_t q67 = f2e4m3x2(v1.z * s, v1.w * s);
    uint2 w;
    w.x = q01 | (q23 << 16);
    w.y = q45 | (q67 << 16);
    *reinterpret_cast<uint2*>(dst + (size_t)row * DDIM + lane * 8) = w;
}

// ---------------------------------------------------------------------------
// Kernel 2: persistent fp8 GEMM, 2 CTAs/SM, A resident, B double-buffered.
// Epilogue: direct log2-domain softplus (no abs/max); products of 8 paired
// into one lg2 per 16 logits. First k-step MMA writes accumulators (no clear).
// ---------------------------------------------------------------------------
__global__ __launch_bounds__(256, 2) void siglip_fp8v11(const float* __restrict__ tprime,
                                                        const float* __restrict__ biasp) {
    extern __shared__ char smem[];
    const uint32_t sb = smem_u32(smem);
    const int tid  = threadIdx.x;
    const int lane = tid & 31;
    const int wid  = tid >> 5;
    const int wr   = wid >> 1;   // 0..3: 32-row slab
    const int wc   = wid & 1;    // 0..1: 64-col slab
    const int cta  = blockIdx.x;

    const int t0 = (int)(((long long)cta * TOTAL_TILES) / NCTA);
    const int t1 = (int)(((long long)(cta + 1) * TOTAL_TILES) / NCTA);

    const float scaleF = __expf(*tprime) * (1.0f / (QSCALE * QSCALE));
    const float bias   = *biasp;
    const float s2 = 1.4426950408889634f * scaleF;   // log2 e * scale
    const float b2 = 1.4426950408889634f * bias;

    // ldmatrix coordinate bases (layout verified R3-R16)
    const int rA0 = wr * 32 + (lane & 7) + (lane & 8);
    const int kAf = (lane & 16);
    const int nB0 = wc * 64 + (lane & 7) + ((lane & 16) >> 1);
    const int kBf = (lane & 8) * 2;

    // swizzle identity: swz(row*128 + c) = row*128 + (c ^ ((row&7)<<4))
    const uint32_t maskA = (uint32_t)((rA0 & 7) << 4);
    const uint32_t maskB = (uint32_t)((nB0 & 7) << 4);
    const uint32_t aRow0 = sb + SM_A + (uint32_t)(rA0 * 128);
    const uint32_t aRow1 = aRow0 + 16 * 128;

    float acc[64];

    // prologue: A(panel of t0) + B(t0)
    {
        const uint8_t* Ag = g_imgQ + (size_t)(t0 >> 7) * TM * DDIM;
        const uint8_t* Bg = g_txtQ + (size_t)(t0 & 127) * TN * DDIM;
        load_tile(sb + SM_A, Ag, tid);
        load_tile(sb + SM_B0 + (uint32_t)(t0 & 1) * 32768u, Bg, tid);
        cpa_commit();
        cpa_wait0();
        __syncthreads();
    }

    double dsum = 0.0;

    for (int t = t0; t < t1; ++t) {
        const uint32_t bbase = sb + SM_B0 + (uint32_t)(t & 1) * 32768u;
        const bool pf = (t + 1 < t1);
        const bool pchange = pf && (((t + 1) >> 7) != (t >> 7));

        if (pf) {
            const uint8_t* Bg = g_txtQ + (size_t)((t + 1) & 127) * TN * DDIM;
            load_tile(sb + SM_B0 + (uint32_t)((t + 1) & 1) * 32768u, Bg, tid);
            cpa_commit();
        }

        // k-loop: 8 steps of k=32B, no syncs inside. ks==0 overwrites acc.
#pragma unroll
        for (int ks = 0; ks < 8; ++ks) {
            const uint32_t stage = (uint32_t)((ks >> 2) << 14);
            const uint32_t kcA = (uint32_t)(((ks & 3) * 32 + kAf)) ^ maskA;
            const uint32_t kcB = (uint32_t)(((ks & 3) * 32 + kBf)) ^ maskB;

            uint32_t a[2][4];
            ldsm_x4(a[0][0], a[0][1], a[0][2], a[0][3], aRow0 + stage + kcA);
            ldsm_x4(a[1][0], a[1][1], a[1][2], a[1][3], aRow1 + stage + kcA);
#pragma unroll
            for (int np = 0; np < 4; ++np) {
                uint32_t b0, b1, b2x, b3;
                uint32_t addr = bbase + (uint32_t)((nB0 + np * 16) * 128) + stage + kcB;
                ldsm_x4(b0, b1, b2x, b3, addr);
#pragma unroll
                for (int mi = 0; mi < 2; ++mi) {
                    float* c0 = &acc[mi * 32 + (2 * np) * 4];
                    float* c1 = &acc[mi * 32 + (2 * np + 1) * 4];
                    if (ks == 0) {
                        mma_fp8_set(c0[0], c0[1], c0[2], c0[3],
                                    a[mi][0], a[mi][1], a[mi][2], a[mi][3], b0, b1);
                        mma_fp8_set(c1[0], c1[1], c1[2], c1[3],
                                    a[mi][0], a[mi][1], a[mi][2], a[mi][3], b2x, b3);
                    } else {
                        mma_fp8(c0[0], c0[1], c0[2], c0[3],
                                a[mi][0], a[mi][1], a[mi][2], a[mi][3], b0, b1);
                        mma_fp8(c1[0], c1[1], c1[2], c1[3],
                                a[mi][0], a[mi][1], a[mi][2], a[mi][3], b2x, b3);
                    }
                }
            }
        }

        // epilogue: softplus(z) = ln2 * log2(1 + 2^zt), zt = s2*acc + b2.
        // |zt| <= ~14 so 2^zt never overflows; two 8-products paired ->
        // one lg2 per 16 logits (pair product bounded ~2^126).
        {
            float fsum = 0.0f;   // log2 units
#pragma unroll
            for (int e = 0; e < 64; e += 16) {
                float u0 = ex2_approx(fmaf(s2, acc[e + 0], b2));
                float u1 = ex2_approx(fmaf(s2, acc[e + 1], b2));
                float u2 = ex2_approx(fmaf(s2, acc[e + 2], b2));
                float u3 = ex2_approx(fmaf(s2, acc[e + 3], b2));
                float u4 = ex2_approx(fmaf(s2, acc[e + 4], b2));
                float u5 = ex2_approx(fmaf(s2, acc[e + 5], b2));
                float u6 = ex2_approx(fmaf(s2, acc[e + 6], b2));
                float u7 = ex2_approx(fmaf(s2, acc[e + 7], b2));
                float p0 = 1.0f + u0;
                p0 = fmaf(p0, u1, p0);
                p0 = fmaf(p0, u2, p0);
                p0 = fmaf(p0, u3, p0);
                p0 = fmaf(p0, u4, p0);
                p0 = fmaf(p0, u5, p0);
                p0 = fmaf(p0, u6, p0);
                p0 = fmaf(p0, u7, p0);
                float v0 = ex2_approx(fmaf(s2, acc[e + 8], b2));
                float v1 = ex2_approx(fmaf(s2, acc[e + 9], b2));
                float v2 = ex2_approx(fmaf(s2, acc[e + 10], b2));
                float v3 = ex2_approx(fmaf(s2, acc[e + 11], b2));
                float v4 = ex2_approx(fmaf(s2, acc[e + 12], b2));
                float v5 = ex2_approx(fmaf(s2, acc[e + 13], b2));
                float v6 = ex2_approx(fmaf(s2, acc[e + 14], b2));
                float v7 = ex2_approx(fmaf(s2, acc[e + 15], b2));
                float p1 = 1.0f + v0;
                p1 = fmaf(p1, v1, p1);
                p1 = fmaf(p1, v2, p1);
                p1 = fmaf(p1, v3, p1);
                p1 = fmaf(p1, v4, p1);
                p1 = fmaf(p1, v5, p1);
                p1 = fmaf(p1, v6, p1);
                p1 = fmaf(p1, v7, p1);
                fsum += lg2_approx(p0 * p1);
            }
            dsum += (double)(LN2 * fsum);
        }

        // exact diagonal correction: softplus(-z) - softplus(z) = -z
        if ((t >> 7) == (t & 127)) {
#pragma unroll
            for (int e = 0; e < 64; ++e) {
                const int mi = e >> 5, ng = (e >> 2) & 7, q = e & 3;
                const int r = wr * 32 + mi * 16 + (lane >> 2) + 8 * (q >> 1);
                const int cI = wc * 64 + ng * 8 + 2 * (lane & 3) + (q & 1);
                if (r == cI) {
                    float z = fmaf(scaleF, acc[e], bias);
                    dsum -= (double)z;
                }
            }
        }

        if (pf) cpa_wait0();
        __syncthreads();

        if (pchange) {   // rare: reload A panel (at most once per CTA)
            const uint8_t* Ag = g_imgQ + (size_t)((t + 1) >> 7) * TM * DDIM;
            load_tile(sb + SM_A, Ag, tid);
            cpa_commit();
            cpa_wait0();
            __syncthreads();
        }
    }

    // deterministic block reduction
#pragma unroll
    for (int o = 16; o > 0; o >>= 1) dsum += __shfl_xor_sync(0xffffffffu, dsum, o);
    double* red = reinterpret_cast<double*>(smem + SM_RED);
    if (lane == 0) red[wid] = dsum;
    __syncthreads();
    if (tid == 0) {
        double s = 0.0;
#pragma unroll
        for (int k = 0; k < 8; ++k) s += red[k];
        g_partials[cta] = s;
    }
}

// ---------------------------------------------------------------------------
// Kernel 3: deterministic final reduction.
// ---------------------------------------------------------------------------
__global__ void reduce_kernel(float* __restrict__ out) {
    __shared__ double sh[512];
    int t = threadIdx.x;
    sh[t]       = (t < NCTA) ? g_partials[t] : 0.0;
    sh[t + 256] = (t + 256 < NCTA) ? g_partials[t + 256] : 0.0;
    __syncthreads();
    if (t < 256) sh[t] += sh[t + 256];
    __syncthreads();
    for (int o = 128; o > 0; o >>= 1) {
        if (t < o) sh[t] += sh[t + o];
        __syncthreads();
    }
    if (t == 0) out[0] = (float)(sh[0] / (double)NROWS);
}

extern "C" void kernel_launch(void* const* d_in, const int* in_sizes, int n_in,
                              void* d_out, int out_size) {
    const float* img    = (const float*)d_in[0];
    const float* txt    = (const float*)d_in[1];
    const float* tprime = (const float*)d_in[2];
    const float* bias   = (const float*)d_in[3];
    float* out = (float*)d_out;

    cudaFuncSetAttribute((const void*)siglip_fp8v11,
                         cudaFuncAttributeMaxDynamicSharedMemorySize, SM_TOTAL);

    normq_kernel<<<dim3(NROWS / 8, 2), 256>>>(img, txt);
    siglip_fp8v11<<<NCTA, 256, SM_TOTAL>>>(tprime, bias);
    reduce_kernel<<<1, 256>>>(out);
}